// round 15
// baseline (speedup 1.0000x reference)
#include <cuda_runtime.h>
#include <cuda_bf16.h>
#include <cuda_fp16.h>
#include <math.h>

// Problem constants
#define IMGS 48
#define H 512
#define W 512
#define IMG_ELEMS (H * W)
#define VALID 506
#define N_TOTAL (48.0 * 512.0 * 512.0)
#define N_SSIM  (48.0 * 506.0 * 506.0)

// Tile: 64x16 outputs, halo 70x22 (72 cols as 36 float2 pairs). 128 threads.
#define TW 64
#define TH 16
#define HH 22
#define PSXY 37
#define THREADS 128
#define GRID_X 8
#define GRID_Y 32
#define BLKS_PER_IMG (GRID_X * GRID_Y)   // 256 ssim blocks per image
#define NSSIM_BLK (BLKS_PER_IMG * IMGS)  // 12288
#define RPI 16                           // range blocks per image
#define NRANGE_BLK (IMGS * RPI)          // 768
#define NBLK_TOTAL (NRANGE_BLK + NSSIM_BLK)

// smem byte layout (fp16 hs planes; all rows 16B-aligned)
#define SXY_BYTES (HH * PSXY * 16)       // 13024
#define HSA_OFF  SXY_BYTES
#define HSROW    272
#define HSB_OFF  (HSA_OFF + HH * HSROW)  // 19008
#define HS1_OFF  (HSB_OFF + HH * HSROW)  // 24992
#define HS1ROW   144
#define SCR_OFF  (HS1_OFF + HH * HS1ROW) // 28160
#define DRED_OFF (SCR_OFF + 128)         // 28288
#define SMEM_BYTES (DRED_OFF + 192)      // 28480 (x8 = 222.5 KB/SM)

// Device scratch (zero-init; last block restores zeros for graph replay)
__device__ float g_pabs[NSSIM_BLK];
__device__ float g_psq[NSSIM_BLK];
__device__ float g_pS[NSSIM_BLK];
__device__ unsigned g_img_max[IMGS];     // fkey(max y); identity 0
__device__ unsigned g_img_negmax[IMGS];  // fkey(-min y); identity 0
__device__ unsigned g_img_cnt[IMGS];
__device__ unsigned g_count;

__device__ __forceinline__ unsigned fkey(float f) {
    unsigned u = __float_as_uint(f);
    return (u & 0x80000000u) ? ~u : (u | 0x80000000u);
}
__device__ __forceinline__ float funkey(unsigned k) {
    unsigned u = (k & 0x80000000u) ? (k & 0x7FFFFFFFu) : ~k;
    return __uint_as_float(u);
}
__device__ __forceinline__ unsigned pack2(float a, float b) {
    __half2 h = __floats2half2_rn(a, b);
    return *reinterpret_cast<unsigned*>(&h);
}

// ---------------------------------------------------------------------------
// Single kernel, block-specialized, 128-thread blocks (8 blocks/SM):
//   blocks [0, 768): per-image range (min/max of y_true*mask), then exit.
//   blocks [768, ..): 64x16 SSIM + MAE/MSE tiles; spin for range AFTER h-pass.
// ---------------------------------------------------------------------------
__global__ void __launch_bounds__(THREADS, 8) k_fused(
    const float* __restrict__ P_, const float* __restrict__ T_,
    const float* __restrict__ M_, float* __restrict__ out)
{
    extern __shared__ char smc[];
    int bid = blockIdx.x;
    int tid = threadIdx.x;
    int lane = tid & 31;
    int warp = tid >> 5;                 // 0..3
    const unsigned F = 0xffffffffu;

    // ================= RANGE BLOCKS =================
    if (bid < NRANGE_BLK) {
        int img = bid >> 4;
        int blk = bid & 15;
        const float4* t4 = (const float4*)(T_ + (size_t)img * IMG_ELEMS);
        const float4* m4 = (const float4*)(M_ + (size_t)img * IMG_ELEMS);
        int base = blk * 4096;           // 4096 float4 per range block

        float mn = INFINITY, mx = -INFINITY;
#pragma unroll 1
        for (int o = 0; o < 32; o += 8) {
#pragma unroll
            for (int i = 0; i < 8; i++) {
                int idx = base + tid + (o + i) * THREADS;
                float4 t = t4[idx];
                float4 m = m4[idx];
                float y0 = t.x * m.x, y1 = t.y * m.y;
                float y2 = t.z * m.z, y3 = t.w * m.w;
                mn = fminf(mn, fminf(fminf(y0, y1), fminf(y2, y3)));
                mx = fmaxf(mx, fmaxf(fmaxf(y0, y1), fmaxf(y2, y3)));
            }
        }
#pragma unroll
        for (int o = 16; o; o >>= 1) {
            mn = fminf(mn, __shfl_down_sync(F, mn, o));
            mx = fmaxf(mx, __shfl_down_sync(F, mx, o));
        }
        __shared__ float wmn[4], wmx[4];
        if (lane == 0) { wmn[warp] = mn; wmx[warp] = mx; }
        __syncthreads();
        if (tid == 0) {
            float MN = INFINITY, MX = -INFINITY;
#pragma unroll
            for (int i = 0; i < 4; i++) {
                MN = fminf(MN, wmn[i]);
                MX = fmaxf(MX, wmx[i]);
            }
            atomicMax(&g_img_max[img], fkey(MX));
            atomicMax(&g_img_negmax[img], fkey(-MN));
            __threadfence();
            atomicAdd(&g_img_cnt[img], 1u);
        }
        return;
    }

    // ================= SSIM BLOCKS =================
    int sid = bid - NRANGE_BLK;
    int img = sid >> 8;                  // 256 blocks per image
    int rr = sid & 255;
    int ox0 = (rr & 7) * TW;
    int oy0 = (rr >> 3) * TH;

    float4* sxy = (float4*)smc;
    char*   hsA = smc + HSA_OFF;
    char*   hsB = smc + HSB_OFF;
    char*   hs1 = smc + HS1_OFF;
    float*  scr = (float*)(smc + SCR_OFF);
    double* dred = (double*)(smc + DRED_OFF);

    const float* Pi = P_ + (size_t)img * IMG_ELEMS;
    const float* Ti = T_ + (size_t)img * IMG_ELEMS;
    const float* Mi = M_ + (size_t)img * IMG_ELEMS;

    // ---- Halo load (batched high-MLP) + MAE/MSE on owned region ----
    // rows: r = warp + 4*it, it = 0..5 (it<4 == owned rows 0..15 exactly)
    float sa = 0.f, sq = 0.f;
    {
        int cmain = min(ox0 + 2 * lane, W - 2);
        bool has_e = lane < 4;
        int cext = min(ox0 + 64 + 2 * (lane & 3), W - 2);

#pragma unroll
        for (int it = 0; it < 6; it++) {
            int r = warp + it * 4;
            if (it == 5 && r >= HH) continue;    // only last iter predicated
            int gy = min(oy0 + r, H - 1);
            const float2* Pr = (const float2*)(Pi + gy * W);
            const float2* Tr = (const float2*)(Ti + gy * W);
            const float2* Mr = (const float2*)(Mi + gy * W);

            float2 p = Pr[cmain >> 1];
            float2 t = Tr[cmain >> 1];
            float2 m = Mr[cmain >> 1];
            float x0 = p.x * m.x, y0 = t.x * m.x;
            float x1 = p.y * m.y, y1 = t.y * m.y;
            sxy[r * PSXY + lane] = make_float4(x0, y0, x1, y1);
            if (it < 4) {                        // owned 64x16 region exactly
                float d0 = x0 - y0, d1 = x1 - y1;
                sa += fabsf(d0) + fabsf(d1);
                sq += d0 * d0 + d1 * d1;
            }
            if (has_e) {
                float2 pe = Pr[cext >> 1];
                float2 te = Tr[cext >> 1];
                float2 me = Mr[cext >> 1];
                sxy[r * PSXY + 32 + (lane & 3)] = make_float4(
                    pe.x * me.x, te.x * me.x, pe.y * me.y, te.y * me.y);
            }
        }
    }
    __syncthreads();

    // ---- Single h-pass: 176 tasks (chunk g 0..7 x row r 0..21) ----
#pragma unroll 1
    for (int l = tid; l < 8 * HH; l += THREADS) {
        int g = l / HH;
        int r = l - g * HH;
        const float4* row = sxy + r * PSXY + g * 4;
        float4 wv[7];
#pragma unroll
        for (int j = 0; j < 7; j++) wv[j] = row[j];

#define PX(p) ((p & 1) ? wv[(p) >> 1].z : wv[(p) >> 1].x)
#define PY(p) ((p & 1) ? wv[(p) >> 1].w : wv[(p) >> 1].y)
        float s0 = 0.f, s1 = 0.f, s2 = 0.f, s3 = 0.f, s4 = 0.f;
#pragma unroll
        for (int j = 0; j < 7; j++) {
            float x = PX(j), y = PY(j);
            s0 += x; s1 += y; s2 += x * x; s3 += y * y; s4 += x * y;
        }
        unsigned pa[8], pb[8];
        float s4v[8];
        pa[0] = pack2(s0, s1); pb[0] = pack2(s2, s3); s4v[0] = s4;
#pragma unroll
        for (int j = 1; j < 8; j++) {
            float xa = PX(6 + j), ya = PY(6 + j);
            float xd = PX(j - 1), yd = PY(j - 1);
            s0 += xa - xd;
            s1 += ya - yd;
            s2 += xa * xa - xd * xd;
            s3 += ya * ya - yd * yd;
            s4 += xa * ya - xd * yd;
            pa[j] = pack2(s0, s1);
            pb[j] = pack2(s2, s3);
            s4v[j] = s4;
        }
#undef PX
#undef PY
        uint4* oA = (uint4*)(hsA + r * HSROW + g * 32);
        uint4* oB = (uint4*)(hsB + r * HSROW + g * 32);
        oA[0] = make_uint4(pa[0], pa[1], pa[2], pa[3]);
        oA[1] = make_uint4(pa[4], pa[5], pa[6], pa[7]);
        oB[0] = make_uint4(pb[0], pb[1], pb[2], pb[3]);
        oB[1] = make_uint4(pb[4], pb[5], pb[6], pb[7]);
        uint4* o1 = (uint4*)(hs1 + r * HS1ROW + g * 16);
        o1[0] = make_uint4(pack2(s4v[0], s4v[1]), pack2(s4v[2], s4v[3]),
                           pack2(s4v[4], s4v[5]), pack2(s4v[6], s4v[7]));
    }
    __syncthreads();

    // ---- Wait for this image's 16 range blocks (early-dispatched, fast) ----
    if (tid == 0) {
        while (*(volatile unsigned*)&g_img_cnt[img] < RPI)
            __nanosleep(64);
        __threadfence();
        float d = funkey(*(volatile unsigned*)&g_img_max[img])
                + funkey(*(volatile unsigned*)&g_img_negmax[img]);
        float c1 = 0.01f * d, c2 = 0.03f * d;
        scr[24] = c1 * c1;
        scr[25] = c2 * c2;
    }
    __syncthreads();
    float C1 = scr[24], C2 = scr[25];

    // ---- v-pass: tx = col (64), ty (2) -> rows ty*8..ty*8+7 (fp16 ring) ----
    float lsum = 0.f;
    {
        int tx = tid & 63;
        int ty = tid >> 6;               // 0..1
        int r0 = ty * 8;

        __half2 bA[7], bB[7];
        __half  b4[7];
        __half2 tA = __floats2half2_rn(0.f, 0.f);
        __half2 tB = tA;
        __half  t4h = __float2half(0.f);
        bA[6] = tA; bB[6] = tA; b4[6] = t4h;
#pragma unroll
        for (int j = 0; j < 6; j++) {
            int r = r0 + j;
            __half2 va = *(const __half2*)(hsA + r * HSROW + tx * 4);
            __half2 vb = *(const __half2*)(hsB + r * HSROW + tx * 4);
            __half  vu = *(const __half*)(hs1 + r * HS1ROW + tx * 2);
            bA[j] = va; bB[j] = vb; b4[j] = vu;
            tA = __hadd2(tA, va);
            tB = __hadd2(tB, vb);
            t4h = __hadd(t4h, vu);
        }
        const float iN = 1.f / 2401.f;
        const float k1 = 1.f / 48.f;
        const float k2 = 1.f / (48.f * 49.f);
        int gox = ox0 + tx;
#pragma unroll
        for (int i = 0; i < 8; i++) {
            int slot = (6 + i) % 7;
            int r = r0 + 6 + i;
            __half2 va = *(const __half2*)(hsA + r * HSROW + tx * 4);
            __half2 vb = *(const __half2*)(hsB + r * HSROW + tx * 4);
            __half  vu = *(const __half*)(hs1 + r * HS1ROW + tx * 2);
            tA = __hadd2(tA, __hsub2(va, bA[slot]));
            tB = __hadd2(tB, __hsub2(vb, bB[slot]));
            t4h = __hadd(t4h, __hsub(vu, b4[slot]));
            bA[slot] = va; bB[slot] = vb; b4[slot] = vu;
            int goy = oy0 + r0 + i;
            if (gox < VALID && goy < VALID) {
                float2 f01 = __half22float2(tA);
                float2 f23 = __half22float2(tB);
                float t4f = __half2float(t4h);
                float p = f01.x * f01.y;
                float q = f01.x * f01.x + f01.y * f01.y;
                float A1 = fmaf(2.f * iN, p, C1);
                float B1 = fmaf(iN, q, C1);
                float A2 = fmaf(2.f * k1, t4f, fmaf(-2.f * k2, p, C2));
                float B2 = fmaf(k1, f23.x + f23.y, fmaf(-k2, q, C2));
                lsum += __fdividef(A1 * A2, B1 * B2);
            }
        }
    }

    // ---- Block reduce -> partial stores ----
#pragma unroll
    for (int o = 16; o; o >>= 1) {
        sa += __shfl_down_sync(F, sa, o);
        sq += __shfl_down_sync(F, sq, o);
        lsum += __shfl_down_sync(F, lsum, o);
    }
    __syncthreads();
    if (lane == 0) { scr[warp] = sa; scr[8 + warp] = sq; scr[16 + warp] = lsum; }
    __syncthreads();
    __shared__ bool is_last;
    if (tid == 0) {
        float A = 0.f, Q = 0.f, S = 0.f;
#pragma unroll
        for (int i = 0; i < 4; i++) { A += scr[i]; Q += scr[8 + i]; S += scr[16 + i]; }
        g_pabs[sid] = A;
        g_psq[sid] = Q;
        g_pS[sid] = S;
        __threadfence();
        unsigned old = atomicAdd(&g_count, 1u);
        is_last = (old == NSSIM_BLK - 1);
    }
    __syncthreads();

    // ---- Last ssim block: final reduce, outputs, reset state ----
    if (is_last) {
        double a = 0.0, q = 0.0, s = 0.0;
        for (int i = tid; i < NSSIM_BLK; i += THREADS) {
            a += (double)g_pabs[i];
            q += (double)g_psq[i];
            s += (double)g_pS[i];
        }
#pragma unroll
        for (int o = 16; o; o >>= 1) {
            a += __shfl_down_sync(F, a, o);
            q += __shfl_down_sync(F, q, o);
            s += __shfl_down_sync(F, s, o);
        }
        if (lane == 0) { dred[warp] = a; dred[8 + warp] = q; dred[16 + warp] = s; }
        if (tid < IMGS) {
            g_img_max[tid] = 0u;
            g_img_negmax[tid] = 0u;
            g_img_cnt[tid] = 0u;
        }
        __syncthreads();
        if (tid == 0) {
            double A = 0.0, Q = 0.0, S = 0.0;
#pragma unroll
            for (int i = 0; i < 4; i++) {
                A += dred[i]; Q += dred[8 + i]; S += dred[16 + i];
            }
            double mae = A / N_TOTAL;
            double mse = Q / N_TOTAL;
            double ssim_loss = 1.0 - S / N_SSIM;
            double total = mae + 0.5 * mse + 0.2 * ssim_loss;
            out[0] = (float)total;
            out[1] = (float)mae;
            out[2] = (float)mse;
            out[3] = (float)ssim_loss;
            g_count = 0;
        }
    }
}

// ---------------------------------------------------------------------------
extern "C" void kernel_launch(void* const* d_in, const int* in_sizes, int n_in,
                              void* d_out, int out_size)
{
    const float* y_pred = (const float*)d_in[0];
    const float* y_true = (const float*)d_in[1];
    const float* mask   = (const float*)d_in[2];
    float* out = (float*)d_out;

    cudaFuncSetAttribute(k_fused, cudaFuncAttributeMaxDynamicSharedMemorySize,
                         SMEM_BYTES);

    k_fused<<<NBLK_TOTAL, THREADS, SMEM_BYTES>>>(y_pred, y_true, mask, out);
}

// round 16
// speedup vs baseline: 1.2373x; 1.2373x over previous
#include <cuda_runtime.h>
#include <cuda_bf16.h>
#include <cuda_fp16.h>
#include <math.h>

// Problem constants
#define IMGS 48
#define H 512
#define W 512
#define IMG_ELEMS (H * W)
#define VALID 506
#define N_TOTAL (48.0 * 512.0 * 512.0)
#define N_SSIM  (48.0 * 506.0 * 506.0)

// Tile: 64x32 outputs, halo 70x38 (72 cols as 36 float2 pairs). 256 threads.
#define TW 64
#define TH 32
#define HH 38
#define PSXY 37
#define GRID_X 8
#define GRID_Y 16
#define BLKS_PER_IMG (GRID_X * GRID_Y)   // 128 ssim blocks per image
#define NSSIM_BLK (BLKS_PER_IMG * IMGS)  // 6144
#define RPI 8                            // range blocks per image
#define NRANGE_BLK (IMGS * RPI)          // 384
#define NBLK_TOTAL (NRANGE_BLK + NSSIM_BLK)

// smem byte layout (fp16 hs planes; all rows 16B-aligned)
#define SXY_BYTES (HH * PSXY * 16)       // 22496
#define HSA_OFF  SXY_BYTES
#define HSROW    272
#define HSB_OFF  (HSA_OFF + HH * HSROW)
#define HS1_OFF  (HSB_OFF + HH * HSROW)
#define HS1ROW   144
#define SCR_OFF  (HS1_OFF + HH * HS1ROW)
#define DRED_OFF (SCR_OFF + 128)
#define SMEM_BYTES (DRED_OFF + 192)      // ~47.8 KB

// Device scratch (zero-init; last block restores zeros for graph replay)
__device__ float g_pabs[NSSIM_BLK];
__device__ float g_psq[NSSIM_BLK];
__device__ float g_pS[NSSIM_BLK];
__device__ unsigned g_img_max[IMGS];     // fkey(max y); identity 0
__device__ unsigned g_img_negmax[IMGS];  // fkey(-min y); identity 0
__device__ unsigned g_img_cnt[IMGS];
__device__ unsigned g_count;

__device__ __forceinline__ unsigned fkey(float f) {
    unsigned u = __float_as_uint(f);
    return (u & 0x80000000u) ? ~u : (u | 0x80000000u);
}
__device__ __forceinline__ float funkey(unsigned k) {
    unsigned u = (k & 0x80000000u) ? (k & 0x7FFFFFFFu) : ~k;
    return __uint_as_float(u);
}
__device__ __forceinline__ unsigned pack2(float a, float b) {
    __half2 h = __floats2half2_rn(a, b);
    return *reinterpret_cast<unsigned*>(&h);
}

// ---------------------------------------------------------------------------
// Single kernel, block-specialized (R14 base):
//   blocks [0, 384): per-image range (min/max of y_true*mask), then exit.
//   blocks [384, ..): 64x32 SSIM + MAE/MSE tiles; spin for range AFTER h-pass.
// h-pass uses 16 chunks x 4 outputs (608 tasks) for better 256-thread balance.
// v-pass sliding sums in native half2.
// ---------------------------------------------------------------------------
__global__ void __launch_bounds__(256, 4) k_fused(
    const float* __restrict__ P_, const float* __restrict__ T_,
    const float* __restrict__ M_, float* __restrict__ out)
{
    extern __shared__ char smc[];
    int bid = blockIdx.x;
    int tid = threadIdx.x;
    int lane = tid & 31;
    int warp = tid >> 5;
    const unsigned F = 0xffffffffu;

    // ================= RANGE BLOCKS =================
    if (bid < NRANGE_BLK) {
        int img = bid >> 3;
        int blk = bid & 7;
        const float4* t4 = (const float4*)(T_ + (size_t)img * IMG_ELEMS);
        const float4* m4 = (const float4*)(M_ + (size_t)img * IMG_ELEMS);
        int base = blk * 8192;

        float mn = INFINITY, mx = -INFINITY;
#pragma unroll 1
        for (int o = 0; o < 32; o += 8) {
#pragma unroll
            for (int i = 0; i < 8; i++) {
                int idx = base + tid + (o + i) * 256;
                float4 t = t4[idx];
                float4 m = m4[idx];
                float y0 = t.x * m.x, y1 = t.y * m.y;
                float y2 = t.z * m.z, y3 = t.w * m.w;
                mn = fminf(mn, fminf(fminf(y0, y1), fminf(y2, y3)));
                mx = fmaxf(mx, fmaxf(fmaxf(y0, y1), fmaxf(y2, y3)));
            }
        }
#pragma unroll
        for (int o = 16; o; o >>= 1) {
            mn = fminf(mn, __shfl_down_sync(F, mn, o));
            mx = fmaxf(mx, __shfl_down_sync(F, mx, o));
        }
        __shared__ float wmn[8], wmx[8];
        if (lane == 0) { wmn[warp] = mn; wmx[warp] = mx; }
        __syncthreads();
        if (tid == 0) {
            float MN = INFINITY, MX = -INFINITY;
#pragma unroll
            for (int i = 0; i < 8; i++) {
                MN = fminf(MN, wmn[i]);
                MX = fmaxf(MX, wmx[i]);
            }
            atomicMax(&g_img_max[img], fkey(MX));
            atomicMax(&g_img_negmax[img], fkey(-MN));
            __threadfence();
            atomicAdd(&g_img_cnt[img], 1u);
        }
        return;
    }

    // ================= SSIM BLOCKS =================
    int sid = bid - NRANGE_BLK;
    int img = sid >> 7;
    int rr = sid & 127;
    int ox0 = (rr & 7) * TW;
    int oy0 = (rr >> 3) * TH;

    float4* sxy = (float4*)smc;
    char*   hsA = smc + HSA_OFF;
    char*   hsB = smc + HSB_OFF;
    char*   hs1 = smc + HS1_OFF;
    float*  scr = (float*)(smc + SCR_OFF);
    double* dred = (double*)(smc + DRED_OFF);

    const float* Pi = P_ + (size_t)img * IMG_ELEMS;
    const float* Ti = T_ + (size_t)img * IMG_ELEMS;
    const float* Mi = M_ + (size_t)img * IMG_ELEMS;

    // ---- Halo load (batched high-MLP) + MAE/MSE on owned region ----
    float sa = 0.f, sq = 0.f;
    {
        int cmain = min(ox0 + 2 * lane, W - 2);
        bool has_e = lane < 4;
        int cext = min(ox0 + 64 + 2 * (lane & 3), W - 2);

#pragma unroll
        for (int it = 0; it < 5; it++) {
            int r = warp + it * 8;
            if (it == 4 && r >= HH) continue;
            int gy = min(oy0 + r, H - 1);
            const float2* Pr = (const float2*)(Pi + gy * W);
            const float2* Tr = (const float2*)(Ti + gy * W);
            const float2* Mr = (const float2*)(Mi + gy * W);

            float2 p = Pr[cmain >> 1];
            float2 t = Tr[cmain >> 1];
            float2 m = Mr[cmain >> 1];
            float x0 = p.x * m.x, y0 = t.x * m.x;
            float x1 = p.y * m.y, y1 = t.y * m.y;
            sxy[r * PSXY + lane] = make_float4(x0, y0, x1, y1);
            if (it < 4) {
                float d0 = x0 - y0, d1 = x1 - y1;
                sa += fabsf(d0) + fabsf(d1);
                sq += d0 * d0 + d1 * d1;
            }
            if (has_e) {
                float2 pe = Pr[cext >> 1];
                float2 te = Tr[cext >> 1];
                float2 me = Mr[cext >> 1];
                sxy[r * PSXY + 32 + (lane & 3)] = make_float4(
                    pe.x * me.x, te.x * me.x, pe.y * me.y, te.y * me.y);
            }
        }
    }
    __syncthreads();

    // ---- h-pass: 608 tasks (chunk g 0..15 x row r 0..37), 4 outputs each ----
#pragma unroll 1
    for (int l = tid; l < 16 * HH; l += 256) {
        int g = l / HH;
        int r = l - g * HH;
        const float4* row = sxy + r * PSXY + g * 2;   // pairs 2g..2g+4
        float4 wv[5];
#pragma unroll
        for (int j = 0; j < 5; j++) wv[j] = row[j];

#define PX(p) ((p & 1) ? wv[(p) >> 1].z : wv[(p) >> 1].x)
#define PY(p) ((p & 1) ? wv[(p) >> 1].w : wv[(p) >> 1].y)
        float s0 = 0.f, s1 = 0.f, s2 = 0.f, s3 = 0.f, s4 = 0.f;
#pragma unroll
        for (int j = 0; j < 7; j++) {
            float x = PX(j), y = PY(j);
            s0 += x; s1 += y; s2 += x * x; s3 += y * y; s4 += x * y;
        }
        unsigned pa[4], pb[4];
        float s4v[4];
        pa[0] = pack2(s0, s1); pb[0] = pack2(s2, s3); s4v[0] = s4;
#pragma unroll
        for (int j = 1; j < 4; j++) {
            float xa = PX(6 + j), ya = PY(6 + j);
            float xd = PX(j - 1), yd = PY(j - 1);
            s0 += xa - xd;
            s1 += ya - yd;
            s2 += xa * xa - xd * xd;
            s3 += ya * ya - yd * yd;
            s4 += xa * ya - xd * yd;
            pa[j] = pack2(s0, s1);
            pb[j] = pack2(s2, s3);
            s4v[j] = s4;
        }
#undef PX
#undef PY
        *(uint4*)(hsA + r * HSROW + g * 16) = make_uint4(pa[0], pa[1], pa[2], pa[3]);
        *(uint4*)(hsB + r * HSROW + g * 16) = make_uint4(pb[0], pb[1], pb[2], pb[3]);
        *(uint2*)(hs1 + r * HS1ROW + g * 8) =
            make_uint2(pack2(s4v[0], s4v[1]), pack2(s4v[2], s4v[3]));
    }
    __syncthreads();

    // ---- Wait for this image's 8 range blocks (early-dispatched, fast) ----
    if (tid == 0) {
        while (*(volatile unsigned*)&g_img_cnt[img] < RPI)
            __nanosleep(64);
        __threadfence();
        float d = funkey(*(volatile unsigned*)&g_img_max[img])
                + funkey(*(volatile unsigned*)&g_img_negmax[img]);
        float c1 = 0.01f * d, c2 = 0.03f * d;
        scr[24] = c1 * c1;
        scr[25] = c2 * c2;
    }
    __syncthreads();
    float C1 = scr[24], C2 = scr[25];

    // ---- v-pass: tx = col (64), ty (4) -> rows ty*8..ty*8+7 (fp16 ring) ----
    float lsum = 0.f;
    {
        int tx = tid & 63;
        int ty = tid >> 6;
        int r0 = ty * 8;

        __half2 bA[7], bB[7];
        __half  b4[7];
        __half2 tA = __floats2half2_rn(0.f, 0.f);
        __half2 tB = tA;
        __half  t4h = __float2half(0.f);
        bA[6] = tA; bB[6] = tA; b4[6] = t4h;
#pragma unroll
        for (int j = 0; j < 6; j++) {
            int r = r0 + j;
            __half2 va = *(const __half2*)(hsA + r * HSROW + tx * 4);
            __half2 vb = *(const __half2*)(hsB + r * HSROW + tx * 4);
            __half  vu = *(const __half*)(hs1 + r * HS1ROW + tx * 2);
            bA[j] = va; bB[j] = vb; b4[j] = vu;
            tA = __hadd2(tA, va);
            tB = __hadd2(tB, vb);
            t4h = __hadd(t4h, vu);
        }
        const float iN = 1.f / 2401.f;
        const float k1 = 1.f / 48.f;
        const float k2 = 1.f / (48.f * 49.f);
        int gox = ox0 + tx;
#pragma unroll
        for (int i = 0; i < 8; i++) {
            int slot = (6 + i) % 7;
            int r = r0 + 6 + i;
            __half2 va = *(const __half2*)(hsA + r * HSROW + tx * 4);
            __half2 vb = *(const __half2*)(hsB + r * HSROW + tx * 4);
            __half  vu = *(const __half*)(hs1 + r * HS1ROW + tx * 2);
            tA = __hadd2(tA, __hsub2(va, bA[slot]));
            tB = __hadd2(tB, __hsub2(vb, bB[slot]));
            t4h = __hadd(t4h, __hsub(vu, b4[slot]));
            bA[slot] = va; bB[slot] = vb; b4[slot] = vu;
            int goy = oy0 + r0 + i;
            if (gox < VALID && goy < VALID) {
                float2 f01 = __half22float2(tA);
                float2 f23 = __half22float2(tB);
                float t4f = __half2float(t4h);
                float p = f01.x * f01.y;
                float q = f01.x * f01.x + f01.y * f01.y;
                float A1 = fmaf(2.f * iN, p, C1);
                float B1 = fmaf(iN, q, C1);
                float A2 = fmaf(2.f * k1, t4f, fmaf(-2.f * k2, p, C2));
                float B2 = fmaf(k1, f23.x + f23.y, fmaf(-k2, q, C2));
                lsum += __fdividef(A1 * A2, B1 * B2);
            }
        }
    }

    // ---- Block reduce -> partial stores ----
#pragma unroll
    for (int o = 16; o; o >>= 1) {
        sa += __shfl_down_sync(F, sa, o);
        sq += __shfl_down_sync(F, sq, o);
        lsum += __shfl_down_sync(F, lsum, o);
    }
    __syncthreads();
    if (lane == 0) { scr[warp] = sa; scr[8 + warp] = sq; scr[16 + warp] = lsum; }
    __syncthreads();
    __shared__ bool is_last;
    if (tid == 0) {
        float A = 0.f, Q = 0.f, S = 0.f;
#pragma unroll
        for (int i = 0; i < 8; i++) { A += scr[i]; Q += scr[8 + i]; S += scr[16 + i]; }
        g_pabs[sid] = A;
        g_psq[sid] = Q;
        g_pS[sid] = S;
        __threadfence();
        unsigned old = atomicAdd(&g_count, 1u);
        is_last = (old == NSSIM_BLK - 1);
    }
    __syncthreads();

    // ---- Last ssim block: final reduce, outputs, reset state ----
    if (is_last) {
        double a = 0.0, q = 0.0, s = 0.0;
        for (int i = tid; i < NSSIM_BLK; i += 256) {
            a += (double)g_pabs[i];
            q += (double)g_psq[i];
            s += (double)g_pS[i];
        }
#pragma unroll
        for (int o = 16; o; o >>= 1) {
            a += __shfl_down_sync(F, a, o);
            q += __shfl_down_sync(F, q, o);
            s += __shfl_down_sync(F, s, o);
        }
        if (lane == 0) { dred[warp] = a; dred[8 + warp] = q; dred[16 + warp] = s; }
        if (tid < IMGS) {
            g_img_max[tid] = 0u;
            g_img_negmax[tid] = 0u;
            g_img_cnt[tid] = 0u;
        }
        __syncthreads();
        if (tid == 0) {
            double A = 0.0, Q = 0.0, S = 0.0;
#pragma unroll
            for (int i = 0; i < 8; i++) {
                A += dred[i]; Q += dred[8 + i]; S += dred[16 + i];
            }
            double mae = A / N_TOTAL;
            double mse = Q / N_TOTAL;
            double ssim_loss = 1.0 - S / N_SSIM;
            double total = mae + 0.5 * mse + 0.2 * ssim_loss;
            out[0] = (float)total;
            out[1] = (float)mae;
            out[2] = (float)mse;
            out[3] = (float)ssim_loss;
            g_count = 0;
        }
    }
}

// ---------------------------------------------------------------------------
extern "C" void kernel_launch(void* const* d_in, const int* in_sizes, int n_in,
                              void* d_out, int out_size)
{
    const float* y_pred = (const float*)d_in[0];
    const float* y_true = (const float*)d_in[1];
    const float* mask   = (const float*)d_in[2];
    float* out = (float*)d_out;

    cudaFuncSetAttribute(k_fused, cudaFuncAttributeMaxDynamicSharedMemorySize,
                         SMEM_BYTES);

    k_fused<<<NBLK_TOTAL, 256, SMEM_BYTES>>>(y_pred, y_true, mask, out);
}